// round 1
// baseline (speedup 1.0000x reference)
#include <cuda_runtime.h>
#include <cstddef>

// Problem constants (fixed by the reference)
#define B_  16
#define S_  512
#define D_  1024
#define H_  16
#define DH_ 64

// Scratch (static device globals: allocation-free per harness rules)
__device__ float g_Q[B_ * S_ * D_];
__device__ float g_K[B_ * S_ * D_];
__device__ float g_V[B_ * S_ * D_];
__device__ float g_A[B_ * S_ * D_];

// ---------------------------------------------------------------------------
// SGEMM: C[M,N] = A[M,K] @ W[K,N] + bias[N]   (all row-major, dims % tile == 0)
// 128x128 block tile, BK=16, 256 threads, 8x8 per-thread register tile.
// ---------------------------------------------------------------------------
__global__ __launch_bounds__(256) void sgemm_bias(
    const float* __restrict__ A, const float* __restrict__ W,
    const float* __restrict__ bias, float* __restrict__ C,
    int M, int N, int K)
{
    constexpr int BM = 128, BN = 128, BK = 16;
    __shared__ float As[BK][BM + 4];  // +4 pad: kills transpose-store conflicts
    __shared__ float Ws[BK][BN];

    const int tid = threadIdx.x;
    const int m0 = blockIdx.y * BM;
    const int n0 = blockIdx.x * BN;
    const int ty = tid >> 4;   // 0..15
    const int tx = tid & 15;   // 0..15

    float acc[8][8];
#pragma unroll
    for (int i = 0; i < 8; i++)
#pragma unroll
        for (int j = 0; j < 8; j++) acc[i][j] = 0.f;

    for (int k0 = 0; k0 < K; k0 += BK) {
#pragma unroll
        for (int p = 0; p < 2; p++) {
            int f = tid + p * 256;            // 512 float4 per tile
            int arow = f >> 2, ac4 = f & 3;   // A: 128 rows x 4 float4
            float4 av = *(const float4*)(A + (size_t)(m0 + arow) * K + k0 + ac4 * 4);
            As[ac4 * 4 + 0][arow] = av.x;
            As[ac4 * 4 + 1][arow] = av.y;
            As[ac4 * 4 + 2][arow] = av.z;
            As[ac4 * 4 + 3][arow] = av.w;
            int wrow = f >> 5, wc4 = f & 31;  // W: 16 rows x 32 float4
            *(float4*)(&Ws[wrow][wc4 * 4]) =
                *(const float4*)(W + (size_t)(k0 + wrow) * N + n0 + wc4 * 4);
        }
        __syncthreads();

#pragma unroll
        for (int kk = 0; kk < BK; kk++) {
            float a[8], b[8];
            *(float4*)(a)     = *(float4*)(&As[kk][ty * 8]);
            *(float4*)(a + 4) = *(float4*)(&As[kk][ty * 8 + 4]);
            *(float4*)(b)     = *(float4*)(&Ws[kk][tx * 8]);
            *(float4*)(b + 4) = *(float4*)(&Ws[kk][tx * 8 + 4]);
#pragma unroll
            for (int i = 0; i < 8; i++)
#pragma unroll
                for (int j = 0; j < 8; j++)
                    acc[i][j] = fmaf(a[i], b[j], acc[i][j]);
        }
        __syncthreads();
    }

#pragma unroll
    for (int i = 0; i < 8; i++) {
        int row = m0 + ty * 8 + i;
#pragma unroll
        for (int j4 = 0; j4 < 2; j4++) {
            int col = n0 + tx * 8 + j4 * 4;
            float4 o;
            o.x = acc[i][j4 * 4 + 0] + bias[col + 0];
            o.y = acc[i][j4 * 4 + 1] + bias[col + 1];
            o.z = acc[i][j4 * 4 + 2] + bias[col + 2];
            o.w = acc[i][j4 * 4 + 3] + bias[col + 3];
            *(float4*)(C + (size_t)row * N + col) = o;
        }
    }
}

// ---------------------------------------------------------------------------
// Flash attention, fp32. One thread = one query row. KT=16 key/value rows per
// shared tile. Online softmax; key-padding mask via lengths; early exit past
// the last valid key tile (tiles fully past `len` contribute exactly zero).
// grid: (S/128, H, B), block: 128
// ---------------------------------------------------------------------------
__global__ __launch_bounds__(128) void attn_kernel(
    const float* __restrict__ Q, const float* __restrict__ K,
    const float* __restrict__ V, const int* __restrict__ lengths,
    float* __restrict__ O)
{
    constexpr int KT = 16;
    __shared__ float sK[KT][DH_];
    __shared__ float sV[KT][DH_];

    const int b = blockIdx.z;
    const int h = blockIdx.y;
    const int tid = threadIdx.x;
    const int qrow = blockIdx.x * 128 + tid;
    const int len = lengths[b];

    // load this thread's q row into registers
    const float* qp = Q + ((size_t)(b * S_ + qrow)) * D_ + h * DH_;
    float qr[DH_];
#pragma unroll
    for (int i = 0; i < DH_ / 4; i++) {
        float4 t = *(const float4*)(qp + i * 4);
        qr[i * 4 + 0] = t.x; qr[i * 4 + 1] = t.y;
        qr[i * 4 + 2] = t.z; qr[i * 4 + 3] = t.w;
    }

    float acc[DH_];
#pragma unroll
    for (int d = 0; d < DH_; d++) acc[d] = 0.f;
    float mrun = -1e30f, lrun = 0.f;

    const int jend = ((len + KT - 1) / KT) * KT;  // cover all valid keys
    const int jj_ld = tid >> 3;  // 0..15  (tile row this thread loads)
    const int c4 = tid & 7;      // 0..7   (float4 column group)

    for (int j0 = 0; j0 < jend; j0 += KT) {
        __syncthreads();
        {
            const float* kp = K + ((size_t)(b * S_ + j0 + jj_ld)) * D_ + h * DH_;
            const float* vp = V + ((size_t)(b * S_ + j0 + jj_ld)) * D_ + h * DH_;
#pragma unroll
            for (int i = 0; i < 2; i++) {
                *(float4*)(&sK[jj_ld][(c4 + 8 * i) * 4]) = *(const float4*)(kp + (c4 + 8 * i) * 4);
                *(float4*)(&sV[jj_ld][(c4 + 8 * i) * 4]) = *(const float4*)(vp + (c4 + 8 * i) * 4);
            }
        }
        __syncthreads();

        // scores for this tile (broadcast smem reads: conflict-free)
        float s[KT];
        float mt = -1e30f;
#pragma unroll
        for (int jj = 0; jj < KT; jj++) {
            float dsum = 0.f;
#pragma unroll
            for (int d = 0; d < DH_; d++)
                dsum = fmaf(qr[d], sK[jj][d], dsum);
            float sc = ((j0 + jj) < len) ? dsum * 0.125f : -1e9f;
            s[jj] = sc;
            mt = fmaxf(mt, sc);
        }

        float mnew = fmaxf(mrun, mt);
        float f = __expf(mrun - mnew);
        lrun *= f;
#pragma unroll
        for (int d = 0; d < DH_; d++) acc[d] *= f;
#pragma unroll
        for (int jj = 0; jj < KT; jj++) {
            float p = __expf(s[jj] - mnew);
            lrun += p;
            s[jj] = p;
        }
#pragma unroll
        for (int jj = 0; jj < KT; jj++) {
#pragma unroll
            for (int d = 0; d < DH_; d++)
                acc[d] = fmaf(s[jj], sV[jj][d], acc[d]);
        }
        mrun = mnew;
    }

    float inv = 1.f / lrun;
    float* op = O + ((size_t)(b * S_ + qrow)) * D_ + h * DH_;
#pragma unroll
    for (int i = 0; i < DH_ / 4; i++) {
        float4 t;
        t.x = acc[i * 4 + 0] * inv; t.y = acc[i * 4 + 1] * inv;
        t.z = acc[i * 4 + 2] * inv; t.w = acc[i * 4 + 3] * inv;
        *(float4*)(op + i * 4) = t;
    }
}

// ---------------------------------------------------------------------------
// Launch
// ---------------------------------------------------------------------------
extern "C" void kernel_launch(void* const* d_in, const int* in_sizes, int n_in,
                              void* d_out, int out_size)
{
    (void)in_sizes; (void)n_in; (void)out_size;
    const float* v       = (const float*)d_in[0];
    const int*   lengths = (const int*)  d_in[1];
    const float* Wq      = (const float*)d_in[2];
    const float* bq      = (const float*)d_in[3];
    const float* Wk      = (const float*)d_in[4];
    const float* bk      = (const float*)d_in[5];
    const float* Wv      = (const float*)d_in[6];
    const float* bv      = (const float*)d_in[7];
    const float* Wo      = (const float*)d_in[8];
    const float* bo      = (const float*)d_in[9];
    float* out = (float*)d_out;

    float *qb, *kb, *vb, *ab;
    cudaGetSymbolAddress((void**)&qb, g_Q);
    cudaGetSymbolAddress((void**)&kb, g_K);
    cudaGetSymbolAddress((void**)&vb, g_V);
    cudaGetSymbolAddress((void**)&ab, g_A);

    const int M = B_ * S_;  // 8192
    dim3 gg(D_ / 128, M / 128);  // (8, 64)

    sgemm_bias<<<gg, 256>>>(v, Wq, bq, qb, M, D_, D_);
    sgemm_bias<<<gg, 256>>>(v, Wk, bk, kb, M, D_, D_);
    sgemm_bias<<<gg, 256>>>(v, Wv, bv, vb, M, D_, D_);

    dim3 ga(S_ / 128, H_, B_);   // (4, 16, 16)
    attn_kernel<<<ga, 128>>>(qb, kb, vb, lengths, ab);

    sgemm_bias<<<gg, 256>>>(ab, Wo, bo, out, M, D_, D_);
}